// round 1
// baseline (speedup 1.0000x reference)
#include <cuda_runtime.h>
#include <math.h>

#define N_EMBD 1024
#define NHEAD  16
#define DH     64
#define BATCH  2
#define TSEQ   2048
#define M_TOT  (BATCH * TSEQ)   // 4096

// Scratch (allocation-free rule: __device__ globals)
__device__ float g_q[BATCH * NHEAD * TSEQ * DH];    // (B,H,T,Dh)
__device__ float g_k[BATCH * NHEAD * TSEQ * DH];
__device__ float g_v[BATCH * NHEAD * TSEQ * DH];
__device__ float g_att[M_TOT * N_EMBD];             // (B,T,C) head-concat

// ---------------------------------------------------------------------------
// Kernel 1: fused QKV projection.
// C_total (4096 x 3072):  col n -> tensor = n/1024, h = (n%1024)/64, d = n%64
// B[k][n] = W[tensor][h*1024*64 + k*64 + d]
// Output written directly in (B,H,T,Dh) layout for the attention kernel.
// 128x128x8 tiling, 256 threads, 8x8 per-thread microtile.
// ---------------------------------------------------------------------------
__global__ __launch_bounds__(256) void qkv_gemm(
    const float* __restrict__ X,
    const float* __restrict__ Wq,
    const float* __restrict__ Wk,
    const float* __restrict__ Wv)
{
    __shared__ __align__(16) float As[8][128];   // A^T: [k][row]
    __shared__ __align__(16) float Bs[8][128];   // [k][col]

    const int tid = threadIdx.x;
    const int cn  = blockIdx.x * 128;        // global col in [0,3072)
    const int rm  = blockIdx.y * 128;        // global row in [0,4096)

    const int which = cn >> 10;              // 0=q 1=k 2=v (128 | 1024)
    const float* W  = (which == 0) ? Wq : (which == 1) ? Wk : Wv;
    float* OUT      = (which == 0) ? g_q : (which == 1) ? g_k : g_v;
    const int cnn   = cn & 1023;             // col within selected tensor

    const int trow = tid >> 4;               // 0..15
    const int tcol = tid & 15;               // 0..15

    // A tile load mapping: row = tid/2 (0..127), k-chunk = (tid&1)*4
    const int arow = tid >> 1;
    const int akc  = (tid & 1) * 4;
    // B tile load mapping: k-row = tid/32 (0..7), col-chunk = (tid&31)*4
    const int bkr  = tid >> 5;
    const int bnc  = (tid & 31) * 4;
    const int bn   = cnn + bnc;
    const int bh   = bn >> 6;
    const int bd   = bn & 63;
    const float* Wbase = W + bh * (N_EMBD * DH) + bd;   // + k*DH

    float acc[8][8];
#pragma unroll
    for (int i = 0; i < 8; i++)
#pragma unroll
        for (int j = 0; j < 8; j++) acc[i][j] = 0.0f;

    for (int k0 = 0; k0 < N_EMBD; k0 += 8) {
        float4 av = *(const float4*)(X + (size_t)(rm + arow) * N_EMBD + k0 + akc);
        As[akc + 0][arow] = av.x;
        As[akc + 1][arow] = av.y;
        As[akc + 2][arow] = av.z;
        As[akc + 3][arow] = av.w;
        float4 bv = *(const float4*)(Wbase + (size_t)(k0 + bkr) * DH);
        *(float4*)&Bs[bkr][bnc] = bv;
        __syncthreads();
#pragma unroll
        for (int k = 0; k < 8; k++) {
            float a[8], b[8];
            *(float4*)&a[0] = *(const float4*)&As[k][trow * 4];
            *(float4*)&a[4] = *(const float4*)&As[k][64 + trow * 4];
            *(float4*)&b[0] = *(const float4*)&Bs[k][tcol * 4];
            *(float4*)&b[4] = *(const float4*)&Bs[k][64 + tcol * 4];
#pragma unroll
            for (int i = 0; i < 8; i++)
#pragma unroll
                for (int j = 0; j < 8; j++)
                    acc[i][j] = fmaf(a[i], b[j], acc[i][j]);
        }
        __syncthreads();
    }

    // Scatter-store into (B,H,T,Dh)
#pragma unroll
    for (int ri = 0; ri < 8; ri++) {
        const int r  = rm + ((ri < 4) ? (trow * 4 + ri) : (64 + trow * 4 + ri - 4));
        const int bb = r >> 11;            // / TSEQ
        const int tt = r & (TSEQ - 1);
#pragma unroll
        for (int cj = 0; cj < 8; cj++) {
            const int c  = cnn + ((cj < 4) ? (tcol * 4 + cj) : (64 + tcol * 4 + cj - 4));
            const int hh = c >> 6;
            const int dd = c & 63;
            OUT[(((size_t)(bb * NHEAD + hh)) * TSEQ + tt) * DH + dd] = acc[ri][cj];
        }
    }
}

// ---------------------------------------------------------------------------
// Kernel 2: causal flash attention, fp32.
// grid = (T/64, B*H), 256 threads. Tiles 64(M) x 64(N), Dh = 64.
// smem = exactly 48KB: Q^T + (K^T reused as P^T) + V. Row stats in registers,
// reduced across the 16 threads that share rows via half-warp shuffles.
// Output written in (B,T,C) concat layout for the projection GEMM.
// ---------------------------------------------------------------------------
__global__ __launch_bounds__(256) void flash_attn()
{
    __shared__ __align__(16) float Qt[64][64];   // [d][row]
    __shared__ __align__(16) float KP[64][64];   // K^T: [d][col] -> reused as P^T: [s][r]
    __shared__ __align__(16) float Vs[64][64];   // [s][d]

    const int bh  = blockIdx.y;          // 0..31
    const int mt  = blockIdx.x;          // 0..31
    const int m0  = mt * 64;
    const int tid = threadIdx.x;

    const float* Qb = g_q + (size_t)bh * TSEQ * DH;
    const float* Kb = g_k + (size_t)bh * TSEQ * DH;
    const float* Vb = g_v + (size_t)bh * TSEQ * DH;

    // Load Q tile transposed: 4096 floats / 256 threads = 4 float4 per thread
#pragma unroll
    for (int p = 0; p < 4; p++) {
        const int idx4 = tid + p * 256;
        const int seq  = idx4 >> 4;          // 0..63
        const int d0   = (idx4 & 15) * 4;    // 0..60
        float4 qv = *(const float4*)(Qb + (size_t)(m0 + seq) * DH + d0);
        Qt[d0 + 0][seq] = qv.x;
        Qt[d0 + 1][seq] = qv.y;
        Qt[d0 + 2][seq] = qv.z;
        Qt[d0 + 3][seq] = qv.w;
    }
    __syncthreads();

    const int trow = tid >> 4;   // 0..15 -> rows trow*4 + i
    const int tcol = tid & 15;   // 0..15 -> cols tcol*4 + j

    float acc[4][4];
    float mrow[4], lrow[4];
#pragma unroll
    for (int i = 0; i < 4; i++) {
        mrow[i] = -INFINITY;
        lrow[i] = 0.0f;
#pragma unroll
        for (int j = 0; j < 4; j++) acc[i][j] = 0.0f;
    }
    const float scale = 0.03125f;   // 1024^-0.5  (reference scales by full C)

    for (int jt = 0; jt <= mt; jt++) {
        const int n0 = jt * 64;
        // Load K^T and V tiles
#pragma unroll
        for (int p = 0; p < 4; p++) {
            const int idx4 = tid + p * 256;
            const int seq  = idx4 >> 4;
            const int d0   = (idx4 & 15) * 4;
            float4 kv = *(const float4*)(Kb + (size_t)(n0 + seq) * DH + d0);
            KP[d0 + 0][seq] = kv.x;
            KP[d0 + 1][seq] = kv.y;
            KP[d0 + 2][seq] = kv.z;
            KP[d0 + 3][seq] = kv.w;
            float4 vv = *(const float4*)(Vb + (size_t)(n0 + seq) * DH + d0);
            *(float4*)&Vs[seq][d0] = vv;
        }
        __syncthreads();

        // S = Q K^T
        float s[4][4];
#pragma unroll
        for (int i = 0; i < 4; i++)
#pragma unroll
            for (int j = 0; j < 4; j++) s[i][j] = 0.0f;
#pragma unroll 8
        for (int k = 0; k < 64; k++) {
            float a[4], b[4];
            *(float4*)&a[0] = *(const float4*)&Qt[k][trow * 4];
            *(float4*)&b[0] = *(const float4*)&KP[k][tcol * 4];
#pragma unroll
            for (int i = 0; i < 4; i++)
#pragma unroll
                for (int j = 0; j < 4; j++)
                    s[i][j] = fmaf(a[i], b[j], s[i][j]);
        }

        // scale + causal mask (only the diagonal tile can be masked)
        const bool diag = (jt == mt);
#pragma unroll
        for (int i = 0; i < 4; i++) {
            const int grow = m0 + trow * 4 + i;
#pragma unroll
            for (int j = 0; j < 4; j++) {
                float v = s[i][j] * scale;
                if (diag && (n0 + tcol * 4 + j) > grow) v = -INFINITY;
                s[i][j] = v;
            }
        }

        // online softmax: row max across the 16 lanes sharing these rows
        float mt4[4];
#pragma unroll
        for (int i = 0; i < 4; i++) {
            float m = s[i][0];
            m = fmaxf(m, s[i][1]); m = fmaxf(m, s[i][2]); m = fmaxf(m, s[i][3]);
#pragma unroll
            for (int off = 1; off < 16; off <<= 1)
                m = fmaxf(m, __shfl_xor_sync(0xffffffffu, m, off));
            mt4[i] = m;
        }
        float al[4];
#pragma unroll
        for (int i = 0; i < 4; i++) {
            const float mnew = fmaxf(mrow[i], mt4[i]);
            al[i]  = __expf(mrow[i] - mnew);
            mrow[i] = mnew;
        }
        float rs[4];
#pragma unroll
        for (int i = 0; i < 4; i++) {
            float r = 0.0f;
#pragma unroll
            for (int j = 0; j < 4; j++) {
                const float p = __expf(s[i][j] - mrow[i]);
                s[i][j] = p;
                r += p;
            }
#pragma unroll
            for (int off = 1; off < 16; off <<= 1)
                r += __shfl_xor_sync(0xffffffffu, r, off);
            rs[i] = r;
        }
#pragma unroll
        for (int i = 0; i < 4; i++) {
            lrow[i] = lrow[i] * al[i] + rs[i];
#pragma unroll
            for (int j = 0; j < 4; j++) acc[i][j] *= al[i];
        }

        // write P^T into the K buffer (all S reads done)
        __syncthreads();
#pragma unroll
        for (int j = 0; j < 4; j++)
#pragma unroll
            for (int i = 0; i < 4; i++)
                KP[tcol * 4 + j][trow * 4 + i] = s[i][j];
        __syncthreads();

        // O += P V
#pragma unroll 8
        for (int k = 0; k < 64; k++) {
            float a[4], b[4];
            *(float4*)&a[0] = *(const float4*)&KP[k][trow * 4];
            *(float4*)&b[0] = *(const float4*)&Vs[k][tcol * 4];
#pragma unroll
            for (int i = 0; i < 4; i++)
#pragma unroll
                for (int j = 0; j < 4; j++)
                    acc[i][j] = fmaf(a[i], b[j], acc[i][j]);
        }
        __syncthreads();   // before next tile overwrites KP/Vs
    }

    // finalize + store into concat layout (B,T,C)
    const int bb = bh >> 4;
    const int hh = bh & 15;
#pragma unroll
    for (int i = 0; i < 4; i++) {
        const float rl = 1.0f / lrow[i];
        const size_t row = (size_t)bb * TSEQ + (m0 + trow * 4 + i);
#pragma unroll
        for (int j = 0; j < 4; j++)
            g_att[row * N_EMBD + hh * DH + tcol * 4 + j] = acc[i][j] * rl;
    }
}

// ---------------------------------------------------------------------------
// Kernel 3: output projection + bias.  out = g_att (4096x1024) @ w_proj + b
// ---------------------------------------------------------------------------
__global__ __launch_bounds__(256) void proj_gemm(
    const float* __restrict__ Wp,
    const float* __restrict__ Bp,
    float* __restrict__ OUT)
{
    __shared__ __align__(16) float As[8][128];
    __shared__ __align__(16) float Bs[8][128];

    const int tid = threadIdx.x;
    const int cn  = blockIdx.x * 128;   // [0,1024)
    const int rm  = blockIdx.y * 128;   // [0,4096)

    const int trow = tid >> 4;
    const int tcol = tid & 15;
    const int arow = tid >> 1;
    const int akc  = (tid & 1) * 4;
    const int bkr  = tid >> 5;
    const int bnc  = (tid & 31) * 4;

    float acc[8][8];
#pragma unroll
    for (int i = 0; i < 8; i++)
#pragma unroll
        for (int j = 0; j < 8; j++) acc[i][j] = 0.0f;

    for (int k0 = 0; k0 < N_EMBD; k0 += 8) {
        float4 av = *(const float4*)(g_att + (size_t)(rm + arow) * N_EMBD + k0 + akc);
        As[akc + 0][arow] = av.x;
        As[akc + 1][arow] = av.y;
        As[akc + 2][arow] = av.z;
        As[akc + 3][arow] = av.w;
        float4 bv = *(const float4*)(Wp + (size_t)(k0 + bkr) * N_EMBD + cn + bnc);
        *(float4*)&Bs[bkr][bnc] = bv;
        __syncthreads();
#pragma unroll
        for (int k = 0; k < 8; k++) {
            float a[8], b[8];
            *(float4*)&a[0] = *(const float4*)&As[k][trow * 4];
            *(float4*)&a[4] = *(const float4*)&As[k][64 + trow * 4];
            *(float4*)&b[0] = *(const float4*)&Bs[k][tcol * 4];
            *(float4*)&b[4] = *(const float4*)&Bs[k][64 + tcol * 4];
#pragma unroll
            for (int i = 0; i < 8; i++)
#pragma unroll
                for (int j = 0; j < 8; j++)
                    acc[i][j] = fmaf(a[i], b[j], acc[i][j]);
        }
        __syncthreads();
    }

#pragma unroll
    for (int ri = 0; ri < 8; ri++) {
        const int r = rm + ((ri < 4) ? (trow * 4 + ri) : (64 + trow * 4 + ri - 4));
#pragma unroll
        for (int cj = 0; cj < 8; cj++) {
            const int c = cn + ((cj < 4) ? (tcol * 4 + cj) : (64 + tcol * 4 + cj - 4));
            OUT[(size_t)r * N_EMBD + c] = acc[ri][cj] + Bp[c];
        }
    }
}

extern "C" void kernel_launch(void* const* d_in, const int* in_sizes, int n_in,
                              void* d_out, int out_size)
{
    const float* x  = (const float*)d_in[0];
    const float* wq = (const float*)d_in[1];
    const float* wk = (const float*)d_in[2];
    const float* wv = (const float*)d_in[3];
    const float* wp = (const float*)d_in[4];
    const float* bp = (const float*)d_in[5];
    float* out = (float*)d_out;

    qkv_gemm<<<dim3(3072 / 128, M_TOT / 128), 256>>>(x, wq, wk, wv);
    flash_attn<<<dim3(TSEQ / 64, BATCH * NHEAD), 256>>>();
    proj_gemm<<<dim3(N_EMBD / 128, M_TOT / 128), 256>>>(wp, bp, out);
}

// round 3
// speedup vs baseline: 1.4457x; 1.4457x over previous
#include <cuda_runtime.h>
#include <math.h>
#include <stdint.h>

#define N_EMBD 1024
#define NHEAD  16
#define DH     64
#define BATCH  2
#define TSEQ   2048
#define M_TOT  (BATCH * TSEQ)   // 4096

// Scratch (allocation-free rule: __device__ globals)
__device__ float g_q[BATCH * NHEAD * TSEQ * DH];
__device__ float g_k[BATCH * NHEAD * TSEQ * DH];
__device__ float g_v[BATCH * NHEAD * TSEQ * DH];
__device__ float g_att[M_TOT * N_EMBD];

__device__ __forceinline__ uint32_t f2tf32(float x) {
    uint32_t r;
    asm("cvt.rna.tf32.f32 %0, %1;" : "=r"(r) : "f"(x));
    return r;
}

// m16n8k8 tf32 HMMA, D += A*B  (A row-major, B col-major)
__device__ __forceinline__ void mma1688(float* d, const uint32_t* a, const uint32_t* b) {
    asm volatile(
        "mma.sync.aligned.m16n8k8.row.col.f32.tf32.tf32.f32 "
        "{%0,%1,%2,%3}, {%4,%5,%6,%7}, {%8,%9}, {%0,%1,%2,%3};"
        : "+f"(d[0]), "+f"(d[1]), "+f"(d[2]), "+f"(d[3])
        : "r"(a[0]), "r"(a[1]), "r"(a[2]), "r"(a[3]), "r"(b[0]), "r"(b[1]));
}

// fast exp: magic-number round + degree-5 2^f polynomial; FMA/ALU pipes only.
// Exact 0 for x <= -80 (incl. -inf); inputs are always <= 0 here.
__device__ __forceinline__ float fexp(float x) {
    const float L2E = 1.4426950408889634f;
    float t = fmaf(x, L2E, 12582912.0f);
    float i = t - 12582912.0f;
    float f = fmaf(x, L2E, -i);
    float p =            1.3333434e-3f;
    p = fmaf(p, f, 9.6181291e-3f);
    p = fmaf(p, f, 5.5504108e-2f);
    p = fmaf(p, f, 2.4022651e-1f);
    p = fmaf(p, f, 6.9314718e-1f);
    p = fmaf(p, f, 1.0f);
    int e = __float_as_int(t) - 0x4B400000;
    int r = __float_as_int(p) + (e << 23);
    return (x > -80.0f) ? __int_as_float(r) : 0.0f;
}

// ---------------------------------------------------------------------------
// Dense GEMM via tf32 mma.sync. CTA tile 128x128, K-chunk 32, 8 warps (2m x 4n),
// warp tile 64x32. sA [m][k] pad 36 (frag bank (4r+c): conflict-free),
// sB [k][n] pad 132 (frag bank (4k+n): conflict-free). Both STS.128-filled.
// ---------------------------------------------------------------------------
__global__ __launch_bounds__(256, 2) void qkv_mma(
    const float* __restrict__ X,
    const float* __restrict__ Wq,
    const float* __restrict__ Wk,
    const float* __restrict__ Wv)
{
    __shared__ __align__(16) uint32_t sA[128 * 36];
    __shared__ __align__(16) uint32_t sB[32 * 132];

    const int tid  = threadIdx.x;
    const int wid  = tid >> 5, lane = tid & 31;
    const int wm   = wid >> 2;            // 0..1
    const int wn   = wid & 3;             // 0..3
    const int lr   = lane >> 2;           // 0..7
    const int lc   = lane & 3;            // 0..3
    const int cn   = blockIdx.x * 128;    // [0,3072)
    const int rm   = blockIdx.y * 128;    // [0,4096)
    const int which = cn >> 10;
    const int cnn   = cn & 1023;
    const float* W  = (which == 0) ? Wq : (which == 1) ? Wk : Wv;
    float* OUT      = (which == 0) ? g_q : (which == 1) ? g_k : g_v;

    float acc[4][4][4] = {};

    const int am = tid >> 3;              // A-load row 0..127 (base)
    const int ac4 = tid & 7;              // A-load k-group
    const int bn0 = lane * 4;             // B-load n base
    const int bh  = (cnn + bn0) >> 6;     // head of this 4-col group
    const int bd  = (cnn + bn0) & 63;
    const float* Wb = W + (size_t)bh * (N_EMBD * DH) + bd;

    for (int c = 0; c < 32; c++) {
        const int k0 = c * 32;
        __syncthreads();
#pragma unroll
        for (int i = 0; i < 4; i++) {
            const int m = am + i * 32;
            float4 v = *(const float4*)(X + (size_t)(rm + m) * N_EMBD + k0 + ac4 * 4);
            uint4 t;
            t.x = f2tf32(v.x); t.y = f2tf32(v.y); t.z = f2tf32(v.z); t.w = f2tf32(v.w);
            *(uint4*)&sA[m * 36 + ac4 * 4] = t;
        }
#pragma unroll
        for (int i = 0; i < 4; i++) {
            const int kk = wid + 8 * i;   // 0..31
            float4 v = *(const float4*)(Wb + (size_t)(k0 + kk) * DH);
            uint4 t;
            t.x = f2tf32(v.x); t.y = f2tf32(v.y); t.z = f2tf32(v.z); t.w = f2tf32(v.w);
            *(uint4*)&sB[kk * 132 + bn0] = t;
        }
        __syncthreads();
#pragma unroll
        for (int kb = 0; kb < 4; kb++) {
            const int ka = kb * 8 + lc;
            uint32_t a[4][4], b[4][2];
#pragma unroll
            for (int i = 0; i < 4; i++) {
                const int mr = wm * 64 + i * 16 + lr;
                a[i][0] = sA[mr * 36 + ka];
                a[i][1] = sA[(mr + 8) * 36 + ka];
                a[i][2] = sA[mr * 36 + ka + 4];
                a[i][3] = sA[(mr + 8) * 36 + ka + 4];
            }
#pragma unroll
            for (int j = 0; j < 4; j++) {
                const int nn = wn * 32 + j * 8 + lr;
                b[j][0] = sB[ka * 132 + nn];
                b[j][1] = sB[(ka + 4) * 132 + nn];
            }
#pragma unroll
            for (int i = 0; i < 4; i++)
#pragma unroll
                for (int j = 0; j < 4; j++)
                    mma1688(acc[i][j], a[i], b[j]);
        }
    }

#pragma unroll
    for (int i = 0; i < 4; i++) {
        const int r0 = rm + wm * 64 + i * 16 + lr;
        const int bb = r0 >> 11;
        const int tt = r0 & (TSEQ - 1);
#pragma unroll
        for (int j = 0; j < 4; j++) {
            const int cg = cnn + wn * 32 + j * 8 + 2 * lc;
            const int hh = cg >> 6, dd = cg & 63;
            float* base = OUT + (((size_t)(bb * NHEAD + hh)) * TSEQ + tt) * DH + dd;
            float2 v0 = {acc[i][j][0], acc[i][j][1]};
            float2 v1 = {acc[i][j][2], acc[i][j][3]};
            *(float2*)base = v0;
            *(float2*)(base + 8 * DH) = v1;
        }
    }
}

__global__ __launch_bounds__(256, 2) void proj_mma(
    const float* __restrict__ Wp,
    const float* __restrict__ Bp,
    float* __restrict__ OUTP)
{
    __shared__ __align__(16) uint32_t sA[128 * 36];
    __shared__ __align__(16) uint32_t sB[32 * 132];

    const int tid  = threadIdx.x;
    const int wid  = tid >> 5, lane = tid & 31;
    const int wm   = wid >> 2;
    const int wn   = wid & 3;
    const int lr   = lane >> 2;
    const int lc   = lane & 3;
    const int cn   = blockIdx.x * 128;   // [0,1024)
    const int rm   = blockIdx.y * 128;   // [0,4096)

    float acc[4][4][4] = {};

    const int am = tid >> 3;
    const int ac4 = tid & 7;
    const int bn0 = lane * 4;

    for (int c = 0; c < 32; c++) {
        const int k0 = c * 32;
        __syncthreads();
#pragma unroll
        for (int i = 0; i < 4; i++) {
            const int m = am + i * 32;
            float4 v = *(const float4*)(g_att + (size_t)(rm + m) * N_EMBD + k0 + ac4 * 4);
            uint4 t;
            t.x = f2tf32(v.x); t.y = f2tf32(v.y); t.z = f2tf32(v.z); t.w = f2tf32(v.w);
            *(uint4*)&sA[m * 36 + ac4 * 4] = t;
        }
#pragma unroll
        for (int i = 0; i < 4; i++) {
            const int kk = wid + 8 * i;
            float4 v = *(const float4*)(Wp + (size_t)(k0 + kk) * N_EMBD + cn + bn0);
            uint4 t;
            t.x = f2tf32(v.x); t.y = f2tf32(v.y); t.z = f2tf32(v.z); t.w = f2tf32(v.w);
            *(uint4*)&sB[kk * 132 + bn0] = t;
        }
        __syncthreads();
#pragma unroll
        for (int kb = 0; kb < 4; kb++) {
            const int ka = kb * 8 + lc;
            uint32_t a[4][4], b[4][2];
#pragma unroll
            for (int i = 0; i < 4; i++) {
                const int mr = wm * 64 + i * 16 + lr;
                a[i][0] = sA[mr * 36 + ka];
                a[i][1] = sA[(mr + 8) * 36 + ka];
                a[i][2] = sA[mr * 36 + ka + 4];
                a[i][3] = sA[(mr + 8) * 36 + ka + 4];
            }
#pragma unroll
            for (int j = 0; j < 4; j++) {
                const int nn = wn * 32 + j * 8 + lr;
                b[j][0] = sB[ka * 132 + nn];
                b[j][1] = sB[(ka + 4) * 132 + nn];
            }
#pragma unroll
            for (int i = 0; i < 4; i++)
#pragma unroll
                for (int j = 0; j < 4; j++)
                    mma1688(acc[i][j], a[i], b[j]);
        }
    }

#pragma unroll
    for (int i = 0; i < 4; i++) {
        const int r0 = rm + wm * 64 + i * 16 + lr;
#pragma unroll
        for (int j = 0; j < 4; j++) {
            const int cg = cn + wn * 32 + j * 8 + 2 * lc;
            float2 bv = *(const float2*)(Bp + cg);
            float2 v0 = {acc[i][j][0] + bv.x, acc[i][j][1] + bv.y};
            float2 v1 = {acc[i][j][2] + bv.x, acc[i][j][3] + bv.y};
            *(float2*)(OUTP + (size_t)r0 * N_EMBD + cg) = v0;
            *(float2*)(OUTP + (size_t)(r0 + 8) * N_EMBD + cg) = v1;
        }
    }
}

// ---------------------------------------------------------------------------
// Causal flash attention, fp32 FMA + FMA-based exp (no MUFU).
// ---------------------------------------------------------------------------
__global__ __launch_bounds__(256) void flash_attn()
{
    __shared__ __align__(16) float Qt[64][64];
    __shared__ __align__(16) float KP[64][64];
    __shared__ __align__(16) float Vs[64][64];

    const int bh  = blockIdx.y;
    const int mt  = blockIdx.x;
    const int m0  = mt * 64;
    const int tid = threadIdx.x;

    const float* Qb = g_q + (size_t)bh * TSEQ * DH;
    const float* Kb = g_k + (size_t)bh * TSEQ * DH;
    const float* Vb = g_v + (size_t)bh * TSEQ * DH;

#pragma unroll
    for (int p = 0; p < 4; p++) {
        const int idx4 = tid + p * 256;
        const int seq  = idx4 >> 4;
        const int d0   = (idx4 & 15) * 4;
        float4 qv = *(const float4*)(Qb + (size_t)(m0 + seq) * DH + d0);
        Qt[d0 + 0][seq] = qv.x;
        Qt[d0 + 1][seq] = qv.y;
        Qt[d0 + 2][seq] = qv.z;
        Qt[d0 + 3][seq] = qv.w;
    }
    __syncthreads();

    const int trow = tid >> 4;
    const int tcol = tid & 15;

    float acc[4][4];
    float mrow[4], lrow[4];
#pragma unroll
    for (int i = 0; i < 4; i++) {
        mrow[i] = -INFINITY;
        lrow[i] = 0.0f;
#pragma unroll
        for (int j = 0; j < 4; j++) acc[i][j] = 0.0f;
    }
    const float scale = 0.03125f;   // 1024^-0.5

    for (int jt = 0; jt <= mt; jt++) {
        const int n0 = jt * 64;
#pragma unroll
        for (int p = 0; p < 4; p++) {
            const int idx4 = tid + p * 256;
            const int seq  = idx4 >> 4;
            const int d0   = (idx4 & 15) * 4;
            float4 kv = *(const float4*)(Kb + (size_t)(n0 + seq) * DH + d0);
            KP[d0 + 0][seq] = kv.x;
            KP[d0 + 1][seq] = kv.y;
            KP[d0 + 2][seq] = kv.z;
            KP[d0 + 3][seq] = kv.w;
            float4 vv = *(const float4*)(Vb + (size_t)(n0 + seq) * DH + d0);
            *(float4*)&Vs[seq][d0] = vv;
        }
        __syncthreads();

        float s[4][4];
#pragma unroll
        for (int i = 0; i < 4; i++)
#pragma unroll
            for (int j = 0; j < 4; j++) s[i][j] = 0.0f;
#pragma unroll 8
        for (int k = 0; k < 64; k++) {
            float a[4], b[4];
            *(float4*)&a[0] = *(const float4*)&Qt[k][trow * 4];
            *(float4*)&b[0] = *(const float4*)&KP[k][tcol * 4];
#pragma unroll
            for (int i = 0; i < 4; i++)
#pragma unroll
                for (int j = 0; j < 4; j++)
                    s[i][j] = fmaf(a[i], b[j], s[i][j]);
        }

        const bool diag = (jt == mt);
#pragma unroll
        for (int i = 0; i < 4; i++) {
            const int grow = m0 + trow * 4 + i;
#pragma unroll
            for (int j = 0; j < 4; j++) {
                float v = s[i][j] * scale;
                if (diag && (n0 + tcol * 4 + j) > grow) v = -INFINITY;
                s[i][j] = v;
            }
        }

        float mt4[4];
#pragma unroll
        for (int i = 0; i < 4; i++) {
            float m = s[i][0];
            m = fmaxf(m, s[i][1]); m = fmaxf(m, s[i][2]); m = fmaxf(m, s[i][3]);
#pragma unroll
            for (int off = 1; off < 16; off <<= 1)
                m = fmaxf(m, __shfl_xor_sync(0xffffffffu, m, off));
            mt4[i] = m;
        }
        float al[4];
#pragma unroll
        for (int i = 0; i < 4; i++) {
            const float mnew = fmaxf(mrow[i], mt4[i]);
            al[i]   = fexp(mrow[i] - mnew);
            mrow[i] = mnew;
        }
        float rs[4];
#pragma unroll
        for (int i = 0; i < 4; i++) {
            float r = 0.0f;
#pragma unroll
            for (int j = 0; j < 4; j++) {
                const float p = fexp(s[i][j] - mrow[i]);
                s[i][j] = p;
                r += p;
            }
#pragma unroll
            for (int off = 1; off < 16; off <<= 1)
                r += __shfl_xor_sync(0xffffffffu, r, off);
            rs[i] = r;
        }
#pragma unroll
        for (int i = 0; i < 4; i++) {
            lrow[i] = lrow[i] * al[i] + rs[i];
#pragma unroll
            for (int j = 0; j < 4; j++) acc[i][j] *= al[i];
        }

        __syncthreads();
#pragma unroll
        for (int j = 0; j < 4; j++)
#pragma unroll
            for (int i = 0; i < 4; i++)
                KP[tcol * 4 + j][trow * 4 + i] = s[i][j];
        __syncthreads();

#pragma unroll 8
        for (int k = 0; k < 64; k++) {
            float a[4], b[4];
            *(float4*)&a[0] = *(const float4*)&KP[k][trow * 4];
            *(float4*)&b[0] = *(const float4*)&Vs[k][tcol * 4];
#pragma unroll
            for (int i = 0; i < 4; i++)
#pragma unroll
                for (int j = 0; j < 4; j++)
                    acc[i][j] = fmaf(a[i], b[j], acc[i][j]);
        }
        __syncthreads();
    }

    const int bb = bh >> 4;
    const int hh = bh & 15;
#pragma unroll
    for (int i = 0; i < 4; i++) {
        const float rl = 1.0f / lrow[i];
        const size_t row = (size_t)bb * TSEQ + (m0 + trow * 4 + i);
#pragma unroll
        for (int j = 0; j < 4; j++)
            g_att[row * N_EMBD + hh * DH + tcol * 4 + j] = acc[i][j] * rl;
    }
}

extern "C" void kernel_launch(void* const* d_in, const int* in_sizes, int n_in,
                              void* d_out, int out_size)
{
    const float* x  = (const float*)d_in[0];
    const float* wq = (const float*)d_in[1];
    const float* wk = (const float*)d_in[2];
    const float* wv = (const float*)d_in[3];
    const float* wp = (const float*)d_in[4];
    const float* bp = (const float*)d_in[5];
    float* out = (float*)d_out;

    qkv_mma<<<dim3(3072 / 128, M_TOT / 128), 256>>>(x, wq, wk, wv);
    flash_attn<<<dim3(TSEQ / 64, BATCH * NHEAD), 256>>>();
    proj_mma<<<dim3(N_EMBD / 128, M_TOT / 128), 256>>>(wp, bp, out);
}

// round 4
// speedup vs baseline: 3.1620x; 2.1872x over previous
#include <cuda_runtime.h>
#include <math.h>
#include <stdint.h>

#define N_EMBD 1024
#define NHEAD  16
#define DH     64
#define BATCH  2
#define TSEQ   2048
#define M_TOT  (BATCH * TSEQ)   // 4096

// Scratch (allocation-free rule: __device__ globals)
__device__ float g_q[BATCH * NHEAD * TSEQ * DH];
__device__ float g_k[BATCH * NHEAD * TSEQ * DH];
__device__ float g_v[BATCH * NHEAD * TSEQ * DH];
__device__ float g_att[M_TOT * N_EMBD];

__device__ __forceinline__ uint32_t f2tf32(float x) {
    uint32_t r;
    asm("cvt.rna.tf32.f32 %0, %1;" : "=r"(r) : "f"(x));
    return r;
}

// m16n8k8 tf32 HMMA, D += A*B  (A row-major, B col-major)
__device__ __forceinline__ void mma1688(float* d, const uint32_t* a, const uint32_t* b) {
    asm volatile(
        "mma.sync.aligned.m16n8k8.row.col.f32.tf32.tf32.f32 "
        "{%0,%1,%2,%3}, {%4,%5,%6,%7}, {%8,%9}, {%0,%1,%2,%3};"
        : "+f"(d[0]), "+f"(d[1]), "+f"(d[2]), "+f"(d[3])
        : "r"(a[0]), "r"(a[1]), "r"(a[2]), "r"(a[3]), "r"(b[0]), "r"(b[1]));
}

// fast exp: magic-number round + degree-5 2^f polynomial; FMA/ALU pipes only.
// Exact 0 for x <= -80 (incl. -inf); inputs are always <= 0 here.
__device__ __forceinline__ float fexp(float x) {
    const float L2E = 1.4426950408889634f;
    float t = fmaf(x, L2E, 12582912.0f);
    float i = t - 12582912.0f;
    float f = fmaf(x, L2E, -i);
    float p =            1.3333434e-3f;
    p = fmaf(p, f, 9.6181291e-3f);
    p = fmaf(p, f, 5.5504108e-2f);
    p = fmaf(p, f, 2.4022651e-1f);
    p = fmaf(p, f, 6.9314718e-1f);
    p = fmaf(p, f, 1.0f);
    int e = __float_as_int(t) - 0x4B400000;
    int r = __float_as_int(p) + (e << 23);
    return (x > -80.0f) ? __int_as_float(r) : 0.0f;
}

// ---------------------------------------------------------------------------
// Dense GEMM via tf32 mma.sync (unchanged from round 3).
// ---------------------------------------------------------------------------
__global__ __launch_bounds__(256, 2) void qkv_mma(
    const float* __restrict__ X,
    const float* __restrict__ Wq,
    const float* __restrict__ Wk,
    const float* __restrict__ Wv)
{
    __shared__ __align__(16) uint32_t sA[128 * 36];
    __shared__ __align__(16) uint32_t sB[32 * 132];

    const int tid  = threadIdx.x;
    const int wid  = tid >> 5, lane = tid & 31;
    const int wm   = wid >> 2;
    const int wn   = wid & 3;
    const int lr   = lane >> 2;
    const int lc   = lane & 3;
    const int cn   = blockIdx.x * 128;
    const int rm   = blockIdx.y * 128;
    const int which = cn >> 10;
    const int cnn   = cn & 1023;
    const float* W  = (which == 0) ? Wq : (which == 1) ? Wk : Wv;
    float* OUT      = (which == 0) ? g_q : (which == 1) ? g_k : g_v;

    float acc[4][4][4] = {};

    const int am = tid >> 3;
    const int ac4 = tid & 7;
    const int bn0 = lane * 4;
    const int bh  = (cnn + bn0) >> 6;
    const int bd  = (cnn + bn0) & 63;
    const float* Wb = W + (size_t)bh * (N_EMBD * DH) + bd;

    for (int c = 0; c < 32; c++) {
        const int k0 = c * 32;
        __syncthreads();
#pragma unroll
        for (int i = 0; i < 4; i++) {
            const int m = am + i * 32;
            float4 v = *(const float4*)(X + (size_t)(rm + m) * N_EMBD + k0 + ac4 * 4);
            uint4 t;
            t.x = f2tf32(v.x); t.y = f2tf32(v.y); t.z = f2tf32(v.z); t.w = f2tf32(v.w);
            *(uint4*)&sA[m * 36 + ac4 * 4] = t;
        }
#pragma unroll
        for (int i = 0; i < 4; i++) {
            const int kk = wid + 8 * i;
            float4 v = *(const float4*)(Wb + (size_t)(k0 + kk) * DH);
            uint4 t;
            t.x = f2tf32(v.x); t.y = f2tf32(v.y); t.z = f2tf32(v.z); t.w = f2tf32(v.w);
            *(uint4*)&sB[kk * 132 + bn0] = t;
        }
        __syncthreads();
#pragma unroll
        for (int kb = 0; kb < 4; kb++) {
            const int ka = kb * 8 + lc;
            uint32_t a[4][4], b[4][2];
#pragma unroll
            for (int i = 0; i < 4; i++) {
                const int mr = wm * 64 + i * 16 + lr;
                a[i][0] = sA[mr * 36 + ka];
                a[i][1] = sA[(mr + 8) * 36 + ka];
                a[i][2] = sA[mr * 36 + ka + 4];
                a[i][3] = sA[(mr + 8) * 36 + ka + 4];
            }
#pragma unroll
            for (int j = 0; j < 4; j++) {
                const int nn = wn * 32 + j * 8 + lr;
                b[j][0] = sB[ka * 132 + nn];
                b[j][1] = sB[(ka + 4) * 132 + nn];
            }
#pragma unroll
            for (int i = 0; i < 4; i++)
#pragma unroll
                for (int j = 0; j < 4; j++)
                    mma1688(acc[i][j], a[i], b[j]);
        }
    }

#pragma unroll
    for (int i = 0; i < 4; i++) {
        const int r0 = rm + wm * 64 + i * 16 + lr;
        const int bb = r0 >> 11;
        const int tt = r0 & (TSEQ - 1);
#pragma unroll
        for (int j = 0; j < 4; j++) {
            const int cg = cnn + wn * 32 + j * 8 + 2 * lc;
            const int hh = cg >> 6, dd = cg & 63;
            float* base = OUT + (((size_t)(bb * NHEAD + hh)) * TSEQ + tt) * DH + dd;
            float2 v0 = {acc[i][j][0], acc[i][j][1]};
            float2 v1 = {acc[i][j][2], acc[i][j][3]};
            *(float2*)base = v0;
            *(float2*)(base + 8 * DH) = v1;
        }
    }
}

__global__ __launch_bounds__(256, 2) void proj_mma(
    const float* __restrict__ Wp,
    const float* __restrict__ Bp,
    float* __restrict__ OUTP)
{
    __shared__ __align__(16) uint32_t sA[128 * 36];
    __shared__ __align__(16) uint32_t sB[32 * 132];

    const int tid  = threadIdx.x;
    const int wid  = tid >> 5, lane = tid & 31;
    const int wm   = wid >> 2;
    const int wn   = wid & 3;
    const int lr   = lane >> 2;
    const int lc   = lane & 3;
    const int cn   = blockIdx.x * 128;
    const int rm   = blockIdx.y * 128;

    float acc[4][4][4] = {};

    const int am = tid >> 3;
    const int ac4 = tid & 7;
    const int bn0 = lane * 4;

    for (int c = 0; c < 32; c++) {
        const int k0 = c * 32;
        __syncthreads();
#pragma unroll
        for (int i = 0; i < 4; i++) {
            const int m = am + i * 32;
            float4 v = *(const float4*)(g_att + (size_t)(rm + m) * N_EMBD + k0 + ac4 * 4);
            uint4 t;
            t.x = f2tf32(v.x); t.y = f2tf32(v.y); t.z = f2tf32(v.z); t.w = f2tf32(v.w);
            *(uint4*)&sA[m * 36 + ac4 * 4] = t;
        }
#pragma unroll
        for (int i = 0; i < 4; i++) {
            const int kk = wid + 8 * i;
            float4 v = *(const float4*)(Wp + (size_t)(k0 + kk) * N_EMBD + cn + bn0);
            uint4 t;
            t.x = f2tf32(v.x); t.y = f2tf32(v.y); t.z = f2tf32(v.z); t.w = f2tf32(v.w);
            *(uint4*)&sB[kk * 132 + bn0] = t;
        }
        __syncthreads();
#pragma unroll
        for (int kb = 0; kb < 4; kb++) {
            const int ka = kb * 8 + lc;
            uint32_t a[4][4], b[4][2];
#pragma unroll
            for (int i = 0; i < 4; i++) {
                const int mr = wm * 64 + i * 16 + lr;
                a[i][0] = sA[mr * 36 + ka];
                a[i][1] = sA[(mr + 8) * 36 + ka];
                a[i][2] = sA[mr * 36 + ka + 4];
                a[i][3] = sA[(mr + 8) * 36 + ka + 4];
            }
#pragma unroll
            for (int j = 0; j < 4; j++) {
                const int nn = wn * 32 + j * 8 + lr;
                b[j][0] = sB[ka * 132 + nn];
                b[j][1] = sB[(ka + 4) * 132 + nn];
            }
#pragma unroll
            for (int i = 0; i < 4; i++)
#pragma unroll
                for (int j = 0; j < 4; j++)
                    mma1688(acc[i][j], a[i], b[j]);
        }
    }

#pragma unroll
    for (int i = 0; i < 4; i++) {
        const int r0 = rm + wm * 64 + i * 16 + lr;
#pragma unroll
        for (int j = 0; j < 4; j++) {
            const int cg = cn + wn * 32 + j * 8 + 2 * lc;
            float2 bv = *(const float2*)(Bp + cg);
            float2 v0 = {acc[i][j][0] + bv.x, acc[i][j][1] + bv.y};
            float2 v1 = {acc[i][j][2] + bv.x, acc[i][j][3] + bv.y};
            *(float2*)(OUTP + (size_t)r0 * N_EMBD + cg) = v0;
            *(float2*)(OUTP + (size_t)(r0 + 8) * N_EMBD + cg) = v1;
        }
    }
}

// ---------------------------------------------------------------------------
// Causal flash attention on tf32 mma.sync.
// CTA: 128 threads / 4 warps, 64 Q-rows (warp = 16), KV tiles of 64.
// Q lives in registers as A-fragments (pre-scaled). K,V in SMEM natural [s][d];
// B-operand col-major indexing gives Q*K^T and P*V with no transposes.
// Softmax on fragment layout; P converted C->A layout via quad shuffles.
// ---------------------------------------------------------------------------
__global__ __launch_bounds__(128, 4) void flash_mma()
{
    __shared__ __align__(16) uint32_t Ks[64 * 68];
    __shared__ __align__(16) uint32_t Vs[64 * 68];

    const int tid  = threadIdx.x;
    const int wid  = tid >> 5;
    const int lane = tid & 31;
    const int g    = lane >> 2;      // 0..7
    const int tig  = lane & 3;       // 0..3
    const int bi   = (int)gridDim.x - 1 - (int)blockIdx.x;   // heavy blocks first
    const int bh   = blockIdx.y;     // 0..31
    const int m0   = bi * 64;

    const float* Qb = g_q + (size_t)bh * TSEQ * DH;
    const float* Kb = g_k + (size_t)bh * TSEQ * DH;
    const float* Vb = g_v + (size_t)bh * TSEQ * DH;

    const int rl0 = wid * 16 + g;    // local row (c0,c1)
    const int rl1 = rl0 + 8;         // local row (c2,c3)
    const float scale = 0.03125f;    // 1024^-0.5 folded into Q

    // Q fragments, resident whole kernel
    uint32_t qf[8][4];
#pragma unroll
    for (int kb = 0; kb < 8; kb++) {
        const float* q0 = Qb + (size_t)(m0 + rl0) * DH + kb * 8 + tig;
        const float* q1 = Qb + (size_t)(m0 + rl1) * DH + kb * 8 + tig;
        qf[kb][0] = f2tf32(q0[0] * scale);
        qf[kb][1] = f2tf32(q1[0] * scale);
        qf[kb][2] = f2tf32(q0[4] * scale);
        qf[kb][3] = f2tf32(q1[4] * scale);
    }

    float oacc[8][4] = {};
    float mr0 = -INFINITY, mr1 = -INFINITY, l0 = 0.0f, l1 = 0.0f;

    const int ntiles = bi + 1;
    for (int jt = 0; jt < ntiles; jt++) {
        const int n0 = jt * 64;
        __syncthreads();   // previous tile's Vs reads done
#pragma unroll
        for (int i = 0; i < 8; i++) {
            const int e  = tid + i * 128;
            const int s  = e >> 4;
            const int d0 = (e & 15) * 4;
            float4 kv = *(const float4*)(Kb + (size_t)(n0 + s) * DH + d0);
            uint4 tk;
            tk.x = f2tf32(kv.x); tk.y = f2tf32(kv.y); tk.z = f2tf32(kv.z); tk.w = f2tf32(kv.w);
            *(uint4*)&Ks[s * 68 + d0] = tk;
            float4 vv = *(const float4*)(Vb + (size_t)(n0 + s) * DH + d0);
            uint4 tv;
            tv.x = f2tf32(vv.x); tv.y = f2tf32(vv.y); tv.z = f2tf32(vv.z); tv.w = f2tf32(vv.w);
            *(uint4*)&Vs[s * 68 + d0] = tv;
        }
        __syncthreads();

        // S = Qscaled * K^T : B[k=d][n=s] = Ks[s][d]
        float sacc[8][4] = {};
#pragma unroll
        for (int kb = 0; kb < 8; kb++) {
            uint32_t b[8][2];
#pragma unroll
            for (int j = 0; j < 8; j++) {
                const int srow = (j * 8 + g) * 68 + kb * 8 + tig;
                b[j][0] = Ks[srow];
                b[j][1] = Ks[srow + 4];
            }
#pragma unroll
            for (int j = 0; j < 8; j++)
                mma1688(sacc[j], qf[kb], b[j]);
        }

        // causal mask (only diagonal tile)
        if (jt == bi) {
#pragma unroll
            for (int j = 0; j < 8; j++) {
                const int cn = j * 8 + 2 * tig;
                if (cn     > rl0) sacc[j][0] = -INFINITY;
                if (cn + 1 > rl0) sacc[j][1] = -INFINITY;
                if (cn     > rl1) sacc[j][2] = -INFINITY;
                if (cn + 1 > rl1) sacc[j][3] = -INFINITY;
            }
        }

        // online softmax on fragment layout
        float mt0 = -INFINITY, mt1 = -INFINITY;
#pragma unroll
        for (int j = 0; j < 8; j++) {
            mt0 = fmaxf(mt0, fmaxf(sacc[j][0], sacc[j][1]));
            mt1 = fmaxf(mt1, fmaxf(sacc[j][2], sacc[j][3]));
        }
        mt0 = fmaxf(mt0, __shfl_xor_sync(0xffffffffu, mt0, 1));
        mt0 = fmaxf(mt0, __shfl_xor_sync(0xffffffffu, mt0, 2));
        mt1 = fmaxf(mt1, __shfl_xor_sync(0xffffffffu, mt1, 1));
        mt1 = fmaxf(mt1, __shfl_xor_sync(0xffffffffu, mt1, 2));

        const float mn0 = fmaxf(mr0, mt0);
        const float mn1 = fmaxf(mr1, mt1);
        const float al0 = fexp(mr0 - mn0);
        const float al1 = fexp(mr1 - mn1);
        mr0 = mn0; mr1 = mn1;

        float rs0 = 0.0f, rs1 = 0.0f;
        uint32_t pf[8][4];
        const int srcA = (lane & 28) | (tig >> 1);
        const bool odd = (tig & 1);
#pragma unroll
        for (int j = 0; j < 8; j++) {
            const float p0 = fexp(sacc[j][0] - mn0);
            const float p1 = fexp(sacc[j][1] - mn0);
            const float p2 = fexp(sacc[j][2] - mn1);
            const float p3 = fexp(sacc[j][3] - mn1);
            rs0 += p0 + p1;
            rs1 += p2 + p3;
            const uint32_t u0 = f2tf32(p0), u1 = f2tf32(p1);
            const uint32_t u2 = f2tf32(p2), u3 = f2tf32(p3);
            // C layout (cols 2*tig, 2*tig+1) -> A layout (cols tig, tig+4)
            uint32_t x0 = __shfl_sync(0xffffffffu, u0, srcA);
            uint32_t x1 = __shfl_sync(0xffffffffu, u1, srcA);
            uint32_t y0 = __shfl_sync(0xffffffffu, u0, srcA + 2);
            uint32_t y1 = __shfl_sync(0xffffffffu, u1, srcA + 2);
            uint32_t x2 = __shfl_sync(0xffffffffu, u2, srcA);
            uint32_t x3 = __shfl_sync(0xffffffffu, u3, srcA);
            uint32_t y2 = __shfl_sync(0xffffffffu, u2, srcA + 2);
            uint32_t y3 = __shfl_sync(0xffffffffu, u3, srcA + 2);
            pf[j][0] = odd ? x1 : x0;
            pf[j][2] = odd ? y1 : y0;
            pf[j][1] = odd ? x3 : x2;
            pf[j][3] = odd ? y3 : y2;
        }
        rs0 += __shfl_xor_sync(0xffffffffu, rs0, 1);
        rs0 += __shfl_xor_sync(0xffffffffu, rs0, 2);
        rs1 += __shfl_xor_sync(0xffffffffu, rs1, 1);
        rs1 += __shfl_xor_sync(0xffffffffu, rs1, 2);
        l0 = l0 * al0 + rs0;
        l1 = l1 * al1 + rs1;
#pragma unroll
        for (int j = 0; j < 8; j++) {
            oacc[j][0] *= al0; oacc[j][1] *= al0;
            oacc[j][2] *= al1; oacc[j][3] *= al1;
        }

        // O += P * V : B[k=s][n=d] = Vs[s][d]
#pragma unroll
        for (int kb = 0; kb < 8; kb++) {
            uint32_t b[8][2];
#pragma unroll
            for (int j = 0; j < 8; j++) {
                const int srow = (kb * 8 + tig) * 68 + j * 8 + g;
                b[j][0] = Vs[srow];
                b[j][1] = Vs[srow + 4 * 68];
            }
#pragma unroll
            for (int j = 0; j < 8; j++)
                mma1688(oacc[j], pf[kb], b[j]);
        }
    }

    // finalize + store into concat layout (B,T,C)
    const float rl0f = 1.0f / l0;
    const float rl1f = 1.0f / l1;
    const int bb = bh >> 4;
    const int hh = bh & 15;
    const size_t row0 = (size_t)bb * TSEQ + (m0 + rl0);
    const size_t row1 = (size_t)bb * TSEQ + (m0 + rl1);
#pragma unroll
    for (int j = 0; j < 8; j++) {
        const int col = hh * DH + j * 8 + 2 * tig;
        float2 v0 = {oacc[j][0] * rl0f, oacc[j][1] * rl0f};
        float2 v1 = {oacc[j][2] * rl1f, oacc[j][3] * rl1f};
        *(float2*)(g_att + row0 * N_EMBD + col) = v0;
        *(float2*)(g_att + row1 * N_EMBD + col) = v1;
    }
}

extern "C" void kernel_launch(void* const* d_in, const int* in_sizes, int n_in,
                              void* d_out, int out_size)
{
    const float* x  = (const float*)d_in[0];
    const float* wq = (const float*)d_in[1];
    const float* wk = (const float*)d_in[2];
    const float* wv = (const float*)d_in[3];
    const float* wp = (const float*)d_in[4];
    const float* bp = (const float*)d_in[5];
    float* out = (float*)d_out;

    qkv_mma<<<dim3(3072 / 128, M_TOT / 128), 256>>>(x, wq, wk, wv);
    flash_mma<<<dim3(TSEQ / 64, BATCH * NHEAD), 128>>>();
    proj_mma<<<dim3(N_EMBD / 128, M_TOT / 128), 256>>>(wp, bp, out);
}